// round 13
// baseline (speedup 1.0000x reference)
#include <cuda_runtime.h>
#include <math.h>

// Problem shapes (fixed by the dataset)
#define BB    2
#define NC    512
#define NF    8192
#define MM    8192
#define NT    256
#define SLICE 512       // targets per block slice
#define NSL   16        // slices (8192 / 512)
#define QPT   4         // queries per thread (main roles)
#define EPSF  1e-12f
#define GX    272       // grid.x
#define GTOT  (GX * BB) // total blocks (544) — all resident (<= 4/SM * 152)

typedef unsigned long long ull;

// ---------------- scratch (__device__ globals; no allocation allowed) ----------------
__device__ float g_av [BB][NSL][NF];     // fine->target partial min value per slice
__device__ int   g_ai [BB][NSL][NF];     // fine->target partial argmin index per slice
__device__ float g_tv [BB][NSL][MM];     // target->fine partial min per slice
__device__ float g_tcv[BB][NSL][MM];     // target->coarse partial min per slice
__device__ float g_cv [BB][NSL][NC];     // coarse->target partial min per slice
__device__ float g_nt [BB * NF * 3];     // gathered nearest target per fine point
__device__ float g_pf [BB][32][4];       // fine combine: sum d1, sum zf^2, sum znt^2, sum ydiff^2
__device__ float g_pt [BB][32][2];       // target combine: sum d2f, sum d2c
__device__ float g_pc [BB][2];           // coarse combine: sum d1c
__device__ float g_pv [BB][32][2];       // volume partials (interior triples)
__device__ unsigned int g_bar;           // grid barrier arrivals (atomicInc wrap -> self-reset)
__device__ unsigned int g_epoch;         // grid barrier release epoch (monotone across replays)
__device__ unsigned int g_ticket;        // finalize ticket (wraps -> self-reset)

// ---------------- packed f32x2 helpers (per-half bit-identical to scalar) ----------------
__device__ __forceinline__ ull pack2(float lo, float hi) {
    ull r; asm("mov.b64 %0, {%1, %2};" : "=l"(r) : "f"(lo), "f"(hi)); return r;
}
__device__ __forceinline__ void unpack2(ull v, float& lo, float& hi) {
    asm("mov.b64 {%0, %1}, %2;" : "=f"(lo), "=f"(hi) : "l"(v));
}
__device__ __forceinline__ ull mul2(ull a, ull b) {
    ull r; asm("mul.rn.f32x2 %0, %1, %2;" : "=l"(r) : "l"(a), "l"(b)); return r;
}
__device__ __forceinline__ ull fma2(ull a, ull b, ull c) {
    ull r; asm("fma.rn.f32x2 %0, %1, %2, %3;" : "=l"(r) : "l"(a), "l"(b), "l"(c)); return r;
}

// Warp sum (fixed shfl order -> deterministic); result valid on lane 0.
__device__ __forceinline__ float warpSum(float v) {
#pragma unroll
    for (int o = 16; o > 0; o >>= 1) v += __shfl_down_sync(0xFFFFFFFFu, v, o);
    return v;
}

// Six block sums with ONE barrier: per-warp shfl trees, leaders write smem,
// tid 0 combines warps in fixed order. Results valid on tid 0 only.
__device__ __forceinline__ void blockSum6(float* v, float (*sh)[6]) {
    const int lane = threadIdx.x & 31;
    const int w    = threadIdx.x >> 5;
#pragma unroll
    for (int i = 0; i < 6; i++) v[i] = warpSum(v[i]);
    if (lane == 0) {
#pragma unroll
        for (int i = 0; i < 6; i++) sh[w][i] = v[i];
    }
    __syncthreads();
    if (threadIdx.x == 0) {
#pragma unroll
        for (int i = 0; i < 6; i++) {
            float r = 0.0f;
#pragma unroll
            for (int k = 0; k < NT / 32; k++) r += sh[k][i];
            v[i] = r;
        }
    }
    __syncthreads();
}

// RAW pairs (argmin role — arithmetic must match the verified form exactly):
__device__ __forceinline__ void loadPairsRaw(ulonglong2* xy, ulonglong2* zw,
                                             const float* __restrict__ src,
                                             int t0, int count) {
    for (int p = threadIdx.x; p < count / 2; p += NT) {
        const int j0 = t0 + 2 * p;
        const float x0 = src[j0 * 3 + 0], y0 = src[j0 * 3 + 1], z0 = src[j0 * 3 + 2];
        const float x1 = src[j0 * 3 + 3], y1 = src[j0 * 3 + 4], z1 = src[j0 * 3 + 5];
        ulonglong2 a, b;
        a.x = pack2(x0, x1); a.y = pack2(y0, y1);
        b.x = pack2(z0, z1);
        b.y = pack2(x0 * x0 + y0 * y0 + z0 * z0,
                    x1 * x1 + y1 * y1 + z1 * z1);
        xy[p] = a; zw[p] = b;
    }
}

// SCALED pairs (min-only roles): store (-2x, -2y, -2z, |p|^2) -> 3 fma2 per pair.
__device__ __forceinline__ void loadPairsScaled(ulonglong2* xy, ulonglong2* zw,
                                                const float* __restrict__ src,
                                                int t0, int count) {
    for (int p = threadIdx.x; p < count / 2; p += NT) {
        const int j0 = t0 + 2 * p;
        const float x0 = src[j0 * 3 + 0], y0 = src[j0 * 3 + 1], z0 = src[j0 * 3 + 2];
        const float x1 = src[j0 * 3 + 3], y1 = src[j0 * 3 + 4], z1 = src[j0 * 3 + 5];
        ulonglong2 a, b;
        a.x = pack2(-2.0f * x0, -2.0f * x1);
        a.y = pack2(-2.0f * y0, -2.0f * y1);
        b.x = pack2(-2.0f * z0, -2.0f * z1);
        b.y = pack2(x0 * x0 + y0 * y0 + z0 * z0,
                    x1 * x1 + y1 * y1 + z1 * z1);
        xy[p] = a; zw[p] = b;
    }
}

// ONE fused kernel. grid = (272, BB), 544 blocks, all resident (<=4/SM).
// Phase 1 = nn slices; device-wide barrier; Phase 2 = combine (blocks 0..65/batch);
// last combine block (ticket) finalizes.
__global__ void __launch_bounds__(NT, 4) fused_kernel(const float* __restrict__ sc,
                                                      const float* __restrict__ sf,
                                                      const float* __restrict__ tp,
                                                      float* __restrict__ out)
{
    __shared__ ulonglong2 tXY[SLICE / 2], tZW[SLICE / 2];
    __shared__ ulonglong2 cXY[16], cZW[16];
    __shared__ float s6[NT / 32][6];
    __shared__ float sfin[NT][3], snt[NT][3];
    __shared__ float svol[BB][2];
    __shared__ bool  s_last;

    const int b   = blockIdx.y;
    const int bx  = blockIdx.x;
    const int tid = threadIdx.x;

    const float* tgt = tp + (size_t)b * MM * 3;
    const float* fin = sf + (size_t)b * NF * 3;
    const float* crs = sc + (size_t)b * NC * 3;

    // ================================ PHASE 1 ================================
    if (bx < 128) {
        // fine -> target : partial argmin over one slice (EXACT verified math)
        const int qb    = bx >> 4;
        const int slice = bx & 15;
        const int base  = slice * SLICE;

        loadPairsRaw(tXY, tZW, tgt, base, SLICE);

        ull qx2[QPT], qy2[QPT], qz2[QPT];
        float best[QPT];
        int   pb[QPT];
#pragma unroll
        for (int q = 0; q < QPT; q++) {
            const int qi = qb * (NT * QPT) + q * NT + tid;
            const float qx = fin[qi * 3 + 0];
            const float qy = fin[qi * 3 + 1];
            const float qz = fin[qi * 3 + 2];
            qx2[q] = pack2(qx, qx); qy2[q] = pack2(qy, qy); qz2[q] = pack2(qz, qz);
            best[q] = 3.0e38f; pb[q] = 0;
        }
        const ull NEG2 = pack2(-2.0f, -2.0f);
        __syncthreads();

#pragma unroll 4
        for (int p = 0; p < SLICE / 2; p++) {
            const ulonglong2 vxy = tXY[p];
            const ulonglong2 vzw = tZW[p];
#pragma unroll
            for (int q = 0; q < QPT; q++) {
                const ull xy2 = fma2(qz2[q], vzw.x, fma2(qy2[q], vxy.y, mul2(qx2[q], vxy.x)));
                const ull t2  = fma2(NEG2, xy2, vzw.y);
                float tlo, thi; unpack2(t2, tlo, thi);
                const float m = fminf(tlo, thi);
                if (m < best[q]) { best[q] = m; pb[q] = p; }
            }
        }
#pragma unroll
        for (int q = 0; q < QPT; q++) {
            const int qi = qb * (NT * QPT) + q * NT + tid;
            const int p = pb[q];
            const ulonglong2 vxy = tXY[p];
            const ulonglong2 vzw = tZW[p];
            const ull xy2 = fma2(qz2[q], vzw.x, fma2(qy2[q], vxy.y, mul2(qx2[q], vxy.x)));
            const ull t2  = fma2(NEG2, xy2, vzw.y);
            float tlo, thi; unpack2(t2, tlo, thi);
            const int jb = base + 2 * p + ((thi < tlo) ? 1 : 0);
            g_av[b][slice][qi] = best[q];
            g_ai[b][slice][qi] = jb;
        }
    } else if (bx < 256) {
        // target -> fine (min) and target -> coarse (min), one slice
        const int r     = bx - 128;
        const int qb    = r >> 4;
        const int slice = r & 15;

        loadPairsScaled(tXY, tZW, fin, slice * SLICE, SLICE);
        loadPairsScaled(cXY, cZW, crs, slice * 32, 32);

        ull qx2[QPT], qy2[QPT], qz2[QPT];
        float mf[QPT * 2], mc[QPT * 2];
#pragma unroll
        for (int q = 0; q < QPT; q++) {
            const int qj = qb * (NT * QPT) + q * NT + tid;
            const float qx = tgt[qj * 3 + 0];
            const float qy = tgt[qj * 3 + 1];
            const float qz = tgt[qj * 3 + 2];
            qx2[q] = pack2(qx, qx); qy2[q] = pack2(qy, qy); qz2[q] = pack2(qz, qz);
            mf[2 * q] = 3.0e38f; mf[2 * q + 1] = 3.0e38f;
            mc[2 * q] = 3.0e38f; mc[2 * q + 1] = 3.0e38f;
        }
        __syncthreads();

#pragma unroll 4
        for (int p = 0; p < SLICE / 2; p++) {
            const ulonglong2 vxy = tXY[p];
            const ulonglong2 vzw = tZW[p];
#pragma unroll
            for (int q = 0; q < QPT; q++) {
                const ull t2 = fma2(qx2[q], vxy.x, fma2(qy2[q], vxy.y, fma2(qz2[q], vzw.x, vzw.y)));
                float tlo, thi; unpack2(t2, tlo, thi);
                mf[2 * q]     = fminf(mf[2 * q],     tlo);
                mf[2 * q + 1] = fminf(mf[2 * q + 1], thi);
            }
        }
#pragma unroll
        for (int p = 0; p < 16; p++) {
            const ulonglong2 vxy = cXY[p];
            const ulonglong2 vzw = cZW[p];
#pragma unroll
            for (int q = 0; q < QPT; q++) {
                const ull t2 = fma2(qx2[q], vxy.x, fma2(qy2[q], vxy.y, fma2(qz2[q], vzw.x, vzw.y)));
                float tlo, thi; unpack2(t2, tlo, thi);
                mc[2 * q]     = fminf(mc[2 * q],     tlo);
                mc[2 * q + 1] = fminf(mc[2 * q + 1], thi);
            }
        }
#pragma unroll
        for (int q = 0; q < QPT; q++) {
            const int qj = qb * (NT * QPT) + q * NT + tid;
            g_tv [b][slice][qj] = fminf(mf[2 * q], mf[2 * q + 1]);
            g_tcv[b][slice][qj] = fminf(mc[2 * q], mc[2 * q + 1]);
        }
    } else {
        // coarse -> target : partial min over one slice
        const int slice = bx - 256;

        loadPairsScaled(tXY, tZW, tgt, slice * SLICE, SLICE);

        ull qx2[2], qy2[2], qz2[2];
        float m[4];
#pragma unroll
        for (int q = 0; q < 2; q++) {
            const int ci = q * NT + tid;
            const float qx = crs[ci * 3 + 0];
            const float qy = crs[ci * 3 + 1];
            const float qz = crs[ci * 3 + 2];
            qx2[q] = pack2(qx, qx); qy2[q] = pack2(qy, qy); qz2[q] = pack2(qz, qz);
            m[2 * q] = 3.0e38f; m[2 * q + 1] = 3.0e38f;
        }
        __syncthreads();

#pragma unroll 4
        for (int p = 0; p < SLICE / 2; p++) {
            const ulonglong2 vxy = tXY[p];
            const ulonglong2 vzw = tZW[p];
#pragma unroll
            for (int q = 0; q < 2; q++) {
                const ull t2 = fma2(qx2[q], vxy.x, fma2(qy2[q], vxy.y, fma2(qz2[q], vzw.x, vzw.y)));
                float tlo, thi; unpack2(t2, tlo, thi);
                m[2 * q]     = fminf(m[2 * q],     tlo);
                m[2 * q + 1] = fminf(m[2 * q + 1], thi);
            }
        }
#pragma unroll
        for (int q = 0; q < 2; q++) {
            const int ci = q * NT + tid;
            g_cv[b][slice][ci] = fminf(m[2 * q], m[2 * q + 1]);
        }
    }

    // ====================== DEVICE-WIDE BARRIER (all resident) ======================
    __threadfence();   // publish phase-1 scratch
    if (tid == 0) {
        volatile unsigned int* ep = &g_epoch;
        const unsigned int ep0 = *ep;
        const unsigned int old = atomicInc(&g_bar, GTOT - 1);  // wraps to 0 -> replay-safe
        if (old == GTOT - 1) {
            atomicAdd(&g_epoch, 1);                            // release (monotone)
        } else {
            while (*ep == ep0) __nanosleep(128);
        }
    }
    __syncthreads();
    __threadfence();   // acquire phase-1 scratch

    // ================================ PHASE 2 ================================
    if (bx >= 66) return;

    float red[6] = {0, 0, 0, 0, 0, 0};

    if (bx < 32) {
        const int qi = bx * NT + tid;
        // tournament on (value, slice): ascending strict < keeps earliest slice
        float best = g_av[b][0][qi]; int sb = 0;
#pragma unroll
        for (int s = 1; s < NSL; s++) {
            const float v = g_av[b][s][qi];
            if (v < best) { best = v; sb = s; }
        }
        const int jb = g_ai[b][sb][qi];

        const float qx = fin[qi * 3 + 0];
        const float qy = fin[qi * 3 + 1];
        const float qz = fin[qi * 3 + 2];
        const float qq = qx * qx + qy * qy + qz * qz;

        const float d  = fmaxf(qq + best, 0.0f);
        const float d1 = sqrtf(fmaxf(d, EPSF));

        const float nx = tgt[jb * 3 + 0];
        const float ny = tgt[jb * 3 + 1];
        const float nz = tgt[jb * 3 + 2];
        const int o = (b * NF + qi) * 3;
        g_nt[o + 0] = nx; g_nt[o + 1] = ny; g_nt[o + 2] = nz;

        sfin[tid][0] = qx; sfin[tid][1] = qy; sfin[tid][2] = qz;
        snt [tid][0] = nx; snt [tid][1] = ny; snt [tid][2] = nz;
        __syncthreads();

        float vf = 0.0f, vn = 0.0f;
        if (tid < NT - 2) {
            float a0 = sfin[tid][0],   a1 = sfin[tid][1],   a2 = sfin[tid][2];
            float e0 = sfin[tid+1][0], e1 = sfin[tid+1][1], e2 = sfin[tid+1][2];
            float c0 = sfin[tid+2][0], c1 = sfin[tid+2][1], c2 = sfin[tid+2][2];
            float cx = a1 * e2 - a2 * e1;
            float cy = a2 * e0 - a0 * e2;
            float cz = a0 * e1 - a1 * e0;
            vf = cx * c0 + cy * c1 + cz * c2;

            a0 = snt[tid][0];   a1 = snt[tid][1];   a2 = snt[tid][2];
            e0 = snt[tid+1][0]; e1 = snt[tid+1][1]; e2 = snt[tid+1][2];
            c0 = snt[tid+2][0]; c1 = snt[tid+2][1]; c2 = snt[tid+2][2];
            cx = a1 * e2 - a2 * e1;
            cy = a2 * e0 - a0 * e2;
            cz = a0 * e1 - a1 * e0;
            vn = cx * c0 + cy * c1 + cz * c2;
        }

        const float yd = qy - ny;
        red[0] = d1; red[1] = qz * qz; red[2] = nz * nz; red[3] = yd * yd;
        red[4] = vf; red[5] = vn;
        blockSum6(red, s6);
        if (tid == 0) {
            g_pf[b][bx][0] = red[0]; g_pf[b][bx][1] = red[1];
            g_pf[b][bx][2] = red[2]; g_pf[b][bx][3] = red[3];
            g_pv[b][bx][0] = red[4]; g_pv[b][bx][1] = red[5];
        }
    } else if (bx < 64) {
        const int qj = (bx - 32) * NT + tid;
        float mF = g_tv[b][0][qj], mC = g_tcv[b][0][qj];
#pragma unroll
        for (int s = 1; s < NSL; s++) {
            mF = fminf(mF, g_tv[b][s][qj]);
            mC = fminf(mC, g_tcv[b][s][qj]);
        }
        const float qx = tgt[qj * 3 + 0];
        const float qy = tgt[qj * 3 + 1];
        const float qz = tgt[qj * 3 + 2];
        const float qq = qx * qx + qy * qy + qz * qz;

        red[0] = sqrtf(fmaxf(fmaxf(qq + mF, 0.0f), EPSF));
        red[1] = sqrtf(fmaxf(fmaxf(qq + mC, 0.0f), EPSF));
        blockSum6(red, s6);
        if (tid == 0) { g_pt[b][bx - 32][0] = red[0]; g_pt[b][bx - 32][1] = red[1]; }
    } else {
        const int ci = (bx - 64) * NT + tid;
        float m = g_cv[b][0][ci];
#pragma unroll
        for (int s = 1; s < NSL; s++) m = fminf(m, g_cv[b][s][ci]);

        const float qx = crs[ci * 3 + 0];
        const float qy = crs[ci * 3 + 1];
        const float qz = crs[ci * 3 + 2];
        const float qq = qx * qx + qy * qy + qz * qz;

        red[0] = sqrtf(fmaxf(fmaxf(qq + m, 0.0f), EPSF));
        blockSum6(red, s6);
        if (tid == 0) g_pc[b][bx - 64] = red[0];
    }

    // ---------------- last-block finalize (ticket among 132) ----------------
    __threadfence();
    if (tid == 0) {
        const unsigned int total = 66 * BB;
        const unsigned int old = atomicInc(&g_ticket, total - 1);
        s_last = (old == total - 1);
    }
    __syncthreads();
    if (!s_last) return;

    // Boundary volume triples: i = 256*k + 254/255, k = 0..30 (62 per batch)
    for (int bb = 0; bb < BB; bb++) {
        float vf = 0.0f, vn = 0.0f;
        for (int t = tid; t < 62; t += NT) {
            const int k = t >> 1;
            const int i = 256 * k + 254 + (t & 1);
            const float* p = sf + (size_t)bb * NF * 3 + (size_t)i * 3;
            float a0 = p[0], a1 = p[1], a2 = p[2];
            float e0 = p[3], e1 = p[4], e2 = p[5];
            float c0 = p[6], c1 = p[7], c2 = p[8];
            float cx = a1 * e2 - a2 * e1;
            float cy = a2 * e0 - a0 * e2;
            float cz = a0 * e1 - a1 * e0;
            vf += cx * c0 + cy * c1 + cz * c2;

            const float* q = g_nt + ((size_t)bb * NF + i) * 3;
            a0 = q[0]; a1 = q[1]; a2 = q[2];
            e0 = q[3]; e1 = q[4]; e2 = q[5];
            c0 = q[6]; c1 = q[7]; c2 = q[8];
            cx = a1 * e2 - a2 * e1;
            cy = a2 * e0 - a0 * e2;
            cz = a0 * e1 - a1 * e0;
            vn += cx * c0 + cy * c1 + cz * c2;
        }
        float rv[6] = {vf, vn, 0, 0, 0, 0};
        blockSum6(rv, s6);
        if (tid == 0) { svol[bb][0] = rv[0]; svol[bb][1] = rv[1]; }
    }
    __syncthreads();

    // Parallel finalize: warp 0, lane k owns partial slot k.
    if (tid < 32) {
        float S1f = 0.0f, Syd = 0.0f, S2f = 0.0f, S2c = 0.0f;
        float szf[BB], sznt[BB], vfb[BB], vnb[BB];
#pragma unroll
        for (int bb = 0; bb < BB; bb++) {
            const float a0 = warpSum(g_pf[bb][tid][0]);
            const float a1 = warpSum(g_pf[bb][tid][1]);
            const float a2 = warpSum(g_pf[bb][tid][2]);
            const float a3 = warpSum(g_pf[bb][tid][3]);
            const float b0 = warpSum(g_pt[bb][tid][0]);
            const float b1 = warpSum(g_pt[bb][tid][1]);
            const float v0 = warpSum(g_pv[bb][tid][0]);
            const float v1 = warpSum(g_pv[bb][tid][1]);
            if (tid == 0) {
                S1f += a0; szf[bb] = a1; sznt[bb] = a2; Syd += a3;
                S2f += b0; S2c += b1;
                vfb[bb] = v0 + svol[bb][0];
                vnb[bb] = v1 + svol[bb][1];
            }
        }
        if (tid == 0) {
            float S1c = 0.0f;
#pragma unroll
            for (int bb = 0; bb < BB; bb++) S1c += g_pc[bb][0] + g_pc[bb][1];

            const float la_f = 0.5f * (S1f / (float)(BB * NF) + S2f / (float)(BB * MM));
            const float la_c = 0.5f * (S1c / (float)(BB * NC) + S2c / (float)(BB * MM));
            const float lref = Syd / (float)(BB * NF);

            float lrot = 0.0f, lgeo = 0.0f;
#pragma unroll
            for (int bb = 0; bb < BB; bb++) {
                const float dr = sqrtf(szf[bb]) - sqrtf(sznt[bb]);
                lrot += dr * dr;
                const float dg = (vfb[bb] - vnb[bb]) * (1.0f / 6.0f);
                lgeo += dg * dg;
            }
            lrot *= (1.0f / (float)BB);
            lgeo *= (1.0f / (float)BB);

            out[0] = lrot + lref + la_c + la_f + lgeo;
        }
    }
}

extern "C" void kernel_launch(void* const* d_in, const int* in_sizes, int n_in,
                              void* d_out, int out_size)
{
    const float* sc = (const float*)d_in[0];  // source_coarse (B, 512, 3)
    const float* sf = (const float*)d_in[1];  // source_fine   (B, 8192, 3)
    const float* tp = (const float*)d_in[2];  // target_points (B, 8192, 3)
    float* out = (float*)d_out;

    dim3 g(GX, BB);
    fused_kernel<<<g, NT>>>(sc, sf, tp, out);
}

// round 15
// speedup vs baseline: 1.0708x; 1.0708x over previous
#include <cuda_runtime.h>
#include <math.h>

// Problem shapes (fixed by the dataset)
#define BB    2
#define NC    512
#define NF    8192
#define MM    8192
#define NT    256
#define SLICE 512       // targets per block slice
#define NSL   16        // slices (8192 / 512)
#define QPT   4         // queries per thread (main roles)
#define EPSF  1e-12f

typedef unsigned long long ull;

// ---------------- scratch (__device__ globals; no allocation allowed) ----------------
__device__ float g_av [BB][NSL][NF];     // fine->target partial min value per slice
__device__ int   g_ai [BB][NSL][NF];     // fine->target partial argmin index per slice
__device__ float g_tv [BB][NSL][MM];     // target->fine partial min per slice
__device__ float g_tcv[BB][NSL][MM];     // target->coarse partial min per slice
__device__ float g_cv [BB][NSL][NC];     // coarse->target partial min per slice
__device__ float g_nt [BB * NF * 3];     // gathered nearest target per fine point
__device__ float g_pf [BB][32][4];       // fine combine: sum d1, sum zf^2, sum znt^2, sum ydiff^2
__device__ float g_pt [BB][32][2];       // target combine: sum d2f, sum d2c
__device__ float g_pc [BB][2];           // coarse combine: sum d1c
__device__ float g_pv [BB][32][2];       // volume partials (interior triples)
__device__ unsigned int g_ticket;        // finalize ticket (wraps -> self-reset)

// ---------------- packed f32x2 helpers (per-half bit-identical to scalar) ----------------
__device__ __forceinline__ ull pack2(float lo, float hi) {
    ull r; asm("mov.b64 %0, {%1, %2};" : "=l"(r) : "f"(lo), "f"(hi)); return r;
}
__device__ __forceinline__ void unpack2(ull v, float& lo, float& hi) {
    asm("mov.b64 {%0, %1}, %2;" : "=f"(lo), "=f"(hi) : "l"(v));
}
__device__ __forceinline__ ull mul2(ull a, ull b) {
    ull r; asm("mul.rn.f32x2 %0, %1, %2;" : "=l"(r) : "l"(a), "l"(b)); return r;
}
__device__ __forceinline__ ull fma2(ull a, ull b, ull c) {
    ull r; asm("fma.rn.f32x2 %0, %1, %2, %3;" : "=l"(r) : "l"(a), "l"(b), "l"(c)); return r;
}

// Warp sum (fixed shfl order -> deterministic); result valid on lane 0.
__device__ __forceinline__ float warpSum(float v) {
#pragma unroll
    for (int o = 16; o > 0; o >>= 1) v += __shfl_down_sync(0xFFFFFFFFu, v, o);
    return v;
}

// Six block sums with ONE barrier. Results valid on tid 0 only.
__device__ __forceinline__ void blockSum6(float* v, float (*sh)[6]) {
    const int lane = threadIdx.x & 31;
    const int w    = threadIdx.x >> 5;
#pragma unroll
    for (int i = 0; i < 6; i++) v[i] = warpSum(v[i]);
    if (lane == 0) {
#pragma unroll
        for (int i = 0; i < 6; i++) sh[w][i] = v[i];
    }
    __syncthreads();
    if (threadIdx.x == 0) {
#pragma unroll
        for (int i = 0; i < 6; i++) {
            float r = 0.0f;
#pragma unroll
            for (int k = 0; k < NT / 32; k++) r += sh[k][i];
            v[i] = r;
        }
    }
    __syncthreads();
}

// RAW pairs (argmin role — arithmetic must match the verified form exactly):
__device__ __forceinline__ void loadPairsRaw(ulonglong2* xy, ulonglong2* zw,
                                             const float* __restrict__ src,
                                             int t0, int count) {
    for (int p = threadIdx.x; p < count / 2; p += NT) {
        const int j0 = t0 + 2 * p;
        const float x0 = src[j0 * 3 + 0], y0 = src[j0 * 3 + 1], z0 = src[j0 * 3 + 2];
        const float x1 = src[j0 * 3 + 3], y1 = src[j0 * 3 + 4], z1 = src[j0 * 3 + 5];
        ulonglong2 a, b;
        a.x = pack2(x0, x1); a.y = pack2(y0, y1);
        b.x = pack2(z0, z1);
        b.y = pack2(x0 * x0 + y0 * y0 + z0 * z0,
                    x1 * x1 + y1 * y1 + z1 * z1);
        xy[p] = a; zw[p] = b;
    }
}

// SCALED pairs (min-only roles): (-2x, -2y, -2z, |p|^2) -> 3 fma2 per pair.
__device__ __forceinline__ void loadPairsScaled(ulonglong2* xy, ulonglong2* zw,
                                                const float* __restrict__ src,
                                                int t0, int count) {
    for (int p = threadIdx.x; p < count / 2; p += NT) {
        const int j0 = t0 + 2 * p;
        const float x0 = src[j0 * 3 + 0], y0 = src[j0 * 3 + 1], z0 = src[j0 * 3 + 2];
        const float x1 = src[j0 * 3 + 3], y1 = src[j0 * 3 + 4], z1 = src[j0 * 3 + 5];
        ulonglong2 a, b;
        a.x = pack2(-2.0f * x0, -2.0f * x1);
        a.y = pack2(-2.0f * y0, -2.0f * y1);
        b.x = pack2(-2.0f * z0, -2.0f * z1);
        b.y = pack2(x0 * x0 + y0 * y0 + z0 * z0,
                    x1 * x1 + y1 * y1 + z1 * z1);
        xy[p] = a; zw[p] = b;
    }
}

// EXACT verified distance for the argmin role:
//   xy = fma(qz,z, fma(qy,y, qx*x)); t = fma(-2, xy, w)
__device__ __forceinline__ ull distExact(ull qx2, ull qy2, ull qz2, ull NEG2,
                                         ulonglong2 vxy, ulonglong2 vzw) {
    const ull xy2 = fma2(qz2, vzw.x, fma2(qy2, vxy.y, mul2(qx2, vxy.x)));
    return fma2(NEG2, xy2, vzw.y);
}

// Main pass: grid = (272, BB).
__global__ void __launch_bounds__(NT) nn_kernel(const float* __restrict__ sc,
                                                const float* __restrict__ sf,
                                                const float* __restrict__ tp)
{
    __shared__ ulonglong2 tXY[SLICE / 2], tZW[SLICE / 2];
    __shared__ ulonglong2 cXY[16], cZW[16];   // coarse sub-slice (32 points)

    const int b   = blockIdx.y;
    const int bx  = blockIdx.x;
    const int tid = threadIdx.x;

    const float* tgt = tp + (size_t)b * MM * 3;
    const float* fin = sf + (size_t)b * NF * 3;
    const float* crs = sc + (size_t)b * NC * 3;

    if (bx < 128) {
        // ====== fine -> target : partial argmin, group-of-2-pairs tournament ======
        // Group g covers pairs p, p+1 (indices 4g..4g+3). One scalar group-min
        // (3 FMNMX) + one compare/select per group. The winning group is recomputed
        // in the epilogue with IDENTICAL arithmetic; first element (ascending index)
        // equal to the group min wins -> exact first-occurrence semantics.
        const int qb    = bx >> 4;
        const int slice = bx & 15;
        const int base  = slice * SLICE;

        loadPairsRaw(tXY, tZW, tgt, base, SLICE);

        ull qx2[QPT], qy2[QPT], qz2[QPT];
        float best[QPT];
        int   pb[QPT];
#pragma unroll
        for (int q = 0; q < QPT; q++) {
            const int qi = qb * (NT * QPT) + q * NT + tid;
            const float qx = fin[qi * 3 + 0];
            const float qy = fin[qi * 3 + 1];
            const float qz = fin[qi * 3 + 2];
            qx2[q] = pack2(qx, qx); qy2[q] = pack2(qy, qy); qz2[q] = pack2(qz, qz);
            best[q] = 3.0e38f; pb[q] = 0;
        }
        const ull NEG2 = pack2(-2.0f, -2.0f);
        __syncthreads();

#pragma unroll 2
        for (int p = 0; p < SLICE / 2; p += 2) {
            const ulonglong2 vxyA = tXY[p],     vzwA = tZW[p];
            const ulonglong2 vxyB = tXY[p + 1], vzwB = tZW[p + 1];
#pragma unroll
            for (int q = 0; q < QPT; q++) {
                const ull tA = distExact(qx2[q], qy2[q], qz2[q], NEG2, vxyA, vzwA);
                const ull tB = distExact(qx2[q], qy2[q], qz2[q], NEG2, vxyB, vzwB);
                float a0, a1, b0, b1;
                unpack2(tA, a0, a1);
                unpack2(tB, b0, b1);
                const float gm = fminf(fminf(a0, a1), fminf(b0, b1));
                if (gm < best[q]) { best[q] = gm; pb[q] = p; }
            }
        }
#pragma unroll
        for (int q = 0; q < QPT; q++) {
            const int qi = qb * (NT * QPT) + q * NT + tid;
            const int p = pb[q];
            const ulonglong2 vxyA = tXY[p],     vzwA = tZW[p];
            const ulonglong2 vxyB = tXY[p + 1], vzwB = tZW[p + 1];
            const ull tA = distExact(qx2[q], qy2[q], qz2[q], NEG2, vxyA, vzwA);
            const ull tB = distExact(qx2[q], qy2[q], qz2[q], NEG2, vxyB, vzwB);
            float a0, a1, b0, b1;
            unpack2(tA, a0, a1);
            unpack2(tB, b0, b1);
            const float m = best[q];
            // first index (ascending) whose distance equals the group min
            int off;
            if      (a0 == m) off = 0;
            else if (a1 == m) off = 1;
            else if (b0 == m) off = 2;
            else              off = 3;
            g_av[b][slice][qi] = m;
            g_ai[b][slice][qi] = base + 2 * p + off;
        }
    } else if (bx < 256) {
        // ====== target -> fine (min) and target -> coarse (min) — verified R12 loop ======
        const int r     = bx - 128;
        const int qb    = r >> 4;
        const int slice = r & 15;

        loadPairsScaled(tXY, tZW, fin, slice * SLICE, SLICE);
        loadPairsScaled(cXY, cZW, crs, slice * 32, 32);

        ull qx2[QPT], qy2[QPT], qz2[QPT];
        float mf[QPT * 2], mc[QPT * 2];
#pragma unroll
        for (int q = 0; q < QPT; q++) {
            const int qj = qb * (NT * QPT) + q * NT + tid;
            const float qx = tgt[qj * 3 + 0];
            const float qy = tgt[qj * 3 + 1];
            const float qz = tgt[qj * 3 + 2];
            qx2[q] = pack2(qx, qx); qy2[q] = pack2(qy, qy); qz2[q] = pack2(qz, qz);
            mf[2 * q] = 3.0e38f; mf[2 * q + 1] = 3.0e38f;
            mc[2 * q] = 3.0e38f; mc[2 * q + 1] = 3.0e38f;
        }
        __syncthreads();

#pragma unroll 4
        for (int p = 0; p < SLICE / 2; p++) {
            const ulonglong2 vxy = tXY[p];
            const ulonglong2 vzw = tZW[p];
#pragma unroll
            for (int q = 0; q < QPT; q++) {
                const ull t2 = fma2(qx2[q], vxy.x, fma2(qy2[q], vxy.y, fma2(qz2[q], vzw.x, vzw.y)));
                float tlo, thi; unpack2(t2, tlo, thi);
                mf[2 * q]     = fminf(mf[2 * q],     tlo);
                mf[2 * q + 1] = fminf(mf[2 * q + 1], thi);
            }
        }
#pragma unroll
        for (int p = 0; p < 16; p++) {
            const ulonglong2 vxy = cXY[p];
            const ulonglong2 vzw = cZW[p];
#pragma unroll
            for (int q = 0; q < QPT; q++) {
                const ull t2 = fma2(qx2[q], vxy.x, fma2(qy2[q], vxy.y, fma2(qz2[q], vzw.x, vzw.y)));
                float tlo, thi; unpack2(t2, tlo, thi);
                mc[2 * q]     = fminf(mc[2 * q],     tlo);
                mc[2 * q + 1] = fminf(mc[2 * q + 1], thi);
            }
        }
#pragma unroll
        for (int q = 0; q < QPT; q++) {
            const int qj = qb * (NT * QPT) + q * NT + tid;
            g_tv [b][slice][qj] = fminf(mf[2 * q], mf[2 * q + 1]);
            g_tcv[b][slice][qj] = fminf(mc[2 * q], mc[2 * q + 1]);
        }
    } else {
        // ================= coarse -> target : partial min — verified R12 loop =================
        const int slice = bx - 256;

        loadPairsScaled(tXY, tZW, tgt, slice * SLICE, SLICE);

        ull qx2[2], qy2[2], qz2[2];
        float m[4];
#pragma unroll
        for (int q = 0; q < 2; q++) {
            const int ci = q * NT + tid;
            const float qx = crs[ci * 3 + 0];
            const float qy = crs[ci * 3 + 1];
            const float qz = crs[ci * 3 + 2];
            qx2[q] = pack2(qx, qx); qy2[q] = pack2(qy, qy); qz2[q] = pack2(qz, qz);
            m[2 * q] = 3.0e38f; m[2 * q + 1] = 3.0e38f;
        }
        __syncthreads();

#pragma unroll 4
        for (int p = 0; p < SLICE / 2; p++) {
            const ulonglong2 vxy = tXY[p];
            const ulonglong2 vzw = tZW[p];
#pragma unroll
            for (int q = 0; q < 2; q++) {
                const ull t2 = fma2(qx2[q], vxy.x, fma2(qy2[q], vxy.y, fma2(qz2[q], vzw.x, vzw.y)));
                float tlo, thi; unpack2(t2, tlo, thi);
                m[2 * q]     = fminf(m[2 * q],     tlo);
                m[2 * q + 1] = fminf(m[2 * q + 1], thi);
            }
        }
#pragma unroll
        for (int q = 0; q < 2; q++) {
            const int ci = q * NT + tid;
            g_cv[b][slice][ci] = fminf(m[2 * q], m[2 * q + 1]);
        }
    }
}

// Combine + fused tail. grid = (66, BB). Last block (ticket) finalizes.
__global__ void __launch_bounds__(NT) combine_kernel(const float* __restrict__ sc,
                                                     const float* __restrict__ sf,
                                                     const float* __restrict__ tp,
                                                     float* __restrict__ out)
{
    __shared__ float s6[NT / 32][6];
    __shared__ float sfin[NT][3], snt[NT][3];
    __shared__ float svol[BB][2];
    __shared__ bool  s_last;
    const int b   = blockIdx.y;
    const int bx  = blockIdx.x;
    const int tid = threadIdx.x;

    float red[6] = {0, 0, 0, 0, 0, 0};

    if (bx < 32) {
        const int qi = bx * NT + tid;
        // tournament on (value, slice): ascending strict < keeps earliest slice
        float best = g_av[b][0][qi]; int sb = 0;
#pragma unroll
        for (int s = 1; s < NSL; s++) {
            const float v = g_av[b][s][qi];
            if (v < best) { best = v; sb = s; }
        }
        const int jb = g_ai[b][sb][qi];

        const float* fin = sf + (size_t)b * NF * 3;
        const float* tgt = tp + (size_t)b * MM * 3;
        const float qx = fin[qi * 3 + 0];
        const float qy = fin[qi * 3 + 1];
        const float qz = fin[qi * 3 + 2];
        const float qq = qx * qx + qy * qy + qz * qz;

        const float d  = fmaxf(qq + best, 0.0f);
        const float d1 = sqrtf(fmaxf(d, EPSF));

        const float nx = tgt[jb * 3 + 0];
        const float ny = tgt[jb * 3 + 1];
        const float nz = tgt[jb * 3 + 2];
        const int o = (b * NF + qi) * 3;
        g_nt[o + 0] = nx; g_nt[o + 1] = ny; g_nt[o + 2] = nz;

        sfin[tid][0] = qx; sfin[tid][1] = qy; sfin[tid][2] = qz;
        snt [tid][0] = nx; snt [tid][1] = ny; snt [tid][2] = nz;
        __syncthreads();

        float vf = 0.0f, vn = 0.0f;
        if (tid < NT - 2) {
            float a0 = sfin[tid][0],   a1 = sfin[tid][1],   a2 = sfin[tid][2];
            float e0 = sfin[tid+1][0], e1 = sfin[tid+1][1], e2 = sfin[tid+1][2];
            float c0 = sfin[tid+2][0], c1 = sfin[tid+2][1], c2 = sfin[tid+2][2];
            float cx = a1 * e2 - a2 * e1;
            float cy = a2 * e0 - a0 * e2;
            float cz = a0 * e1 - a1 * e0;
            vf = cx * c0 + cy * c1 + cz * c2;

            a0 = snt[tid][0];   a1 = snt[tid][1];   a2 = snt[tid][2];
            e0 = snt[tid+1][0]; e1 = snt[tid+1][1]; e2 = snt[tid+1][2];
            c0 = snt[tid+2][0]; c1 = snt[tid+2][1]; c2 = snt[tid+2][2];
            cx = a1 * e2 - a2 * e1;
            cy = a2 * e0 - a0 * e2;
            cz = a0 * e1 - a1 * e0;
            vn = cx * c0 + cy * c1 + cz * c2;
        }

        const float yd = qy - ny;
        red[0] = d1; red[1] = qz * qz; red[2] = nz * nz; red[3] = yd * yd;
        red[4] = vf; red[5] = vn;
        blockSum6(red, s6);
        if (tid == 0) {
            g_pf[b][bx][0] = red[0]; g_pf[b][bx][1] = red[1];
            g_pf[b][bx][2] = red[2]; g_pf[b][bx][3] = red[3];
            g_pv[b][bx][0] = red[4]; g_pv[b][bx][1] = red[5];
        }
    } else if (bx < 64) {
        const int qj = (bx - 32) * NT + tid;
        float mF = g_tv[b][0][qj], mC = g_tcv[b][0][qj];
#pragma unroll
        for (int s = 1; s < NSL; s++) {
            mF = fminf(mF, g_tv[b][s][qj]);
            mC = fminf(mC, g_tcv[b][s][qj]);
        }
        const float* tgt = tp + (size_t)b * MM * 3;
        const float qx = tgt[qj * 3 + 0];
        const float qy = tgt[qj * 3 + 1];
        const float qz = tgt[qj * 3 + 2];
        const float qq = qx * qx + qy * qy + qz * qz;

        red[0] = sqrtf(fmaxf(fmaxf(qq + mF, 0.0f), EPSF));
        red[1] = sqrtf(fmaxf(fmaxf(qq + mC, 0.0f), EPSF));
        blockSum6(red, s6);
        if (tid == 0) { g_pt[b][bx - 32][0] = red[0]; g_pt[b][bx - 32][1] = red[1]; }
    } else {
        const int ci = (bx - 64) * NT + tid;
        float m = g_cv[b][0][ci];
#pragma unroll
        for (int s = 1; s < NSL; s++) m = fminf(m, g_cv[b][s][ci]);

        const float* crs = sc + (size_t)b * NC * 3;
        const float qx = crs[ci * 3 + 0];
        const float qy = crs[ci * 3 + 1];
        const float qz = crs[ci * 3 + 2];
        const float qq = qx * qx + qy * qy + qz * qz;

        red[0] = sqrtf(fmaxf(fmaxf(qq + m, 0.0f), EPSF));
        blockSum6(red, s6);
        if (tid == 0) g_pc[b][bx - 64] = red[0];
    }

    // ---------------- last-block fused tail ----------------
    __threadfence();
    if (tid == 0) {
        const unsigned int total = 66 * BB;
        const unsigned int old = atomicInc(&g_ticket, total - 1);
        s_last = (old == total - 1);
    }
    __syncthreads();
    if (!s_last) return;

    // Boundary volume triples: i = 256*k + 254/255, k = 0..30 (62 per batch)
    for (int bb = 0; bb < BB; bb++) {
        float vf = 0.0f, vn = 0.0f;
        for (int t = tid; t < 62; t += NT) {
            const int k = t >> 1;
            const int i = 256 * k + 254 + (t & 1);
            const float* p = sf + (size_t)bb * NF * 3 + (size_t)i * 3;
            float a0 = p[0], a1 = p[1], a2 = p[2];
            float e0 = p[3], e1 = p[4], e2 = p[5];
            float c0 = p[6], c1 = p[7], c2 = p[8];
            float cx = a1 * e2 - a2 * e1;
            float cy = a2 * e0 - a0 * e2;
            float cz = a0 * e1 - a1 * e0;
            vf += cx * c0 + cy * c1 + cz * c2;

            const float* q = g_nt + ((size_t)bb * NF + i) * 3;
            a0 = q[0]; a1 = q[1]; a2 = q[2];
            e0 = q[3]; e1 = q[4]; e2 = q[5];
            c0 = q[6]; c1 = q[7]; c2 = q[8];
            cx = a1 * e2 - a2 * e1;
            cy = a2 * e0 - a0 * e2;
            cz = a0 * e1 - a1 * e0;
            vn += cx * c0 + cy * c1 + cz * c2;
        }
        float rv[6] = {vf, vn, 0, 0, 0, 0};
        blockSum6(rv, s6);
        if (tid == 0) { svol[bb][0] = rv[0]; svol[bb][1] = rv[1]; }
    }
    __syncthreads();

    // Parallel finalize: warp 0, lane k owns partial slot k.
    if (tid < 32) {
        float S1f = 0.0f, Syd = 0.0f, S2f = 0.0f, S2c = 0.0f;
        float szf[BB], sznt[BB], vfb[BB], vnb[BB];
#pragma unroll
        for (int bb = 0; bb < BB; bb++) {
            const float a0 = warpSum(g_pf[bb][tid][0]);
            const float a1 = warpSum(g_pf[bb][tid][1]);
            const float a2 = warpSum(g_pf[bb][tid][2]);
            const float a3 = warpSum(g_pf[bb][tid][3]);
            const float b0 = warpSum(g_pt[bb][tid][0]);
            const float b1 = warpSum(g_pt[bb][tid][1]);
            const float v0 = warpSum(g_pv[bb][tid][0]);
            const float v1 = warpSum(g_pv[bb][tid][1]);
            if (tid == 0) {
                S1f += a0; szf[bb] = a1; sznt[bb] = a2; Syd += a3;
                S2f += b0; S2c += b1;
                vfb[bb] = v0 + svol[bb][0];
                vnb[bb] = v1 + svol[bb][1];
            }
        }
        if (tid == 0) {
            float S1c = 0.0f;
#pragma unroll
            for (int bb = 0; bb < BB; bb++) S1c += g_pc[bb][0] + g_pc[bb][1];

            const float la_f = 0.5f * (S1f / (float)(BB * NF) + S2f / (float)(BB * MM));
            const float la_c = 0.5f * (S1c / (float)(BB * NC) + S2c / (float)(BB * MM));
            const float lref = Syd / (float)(BB * NF);

            float lrot = 0.0f, lgeo = 0.0f;
#pragma unroll
            for (int bb = 0; bb < BB; bb++) {
                const float dr = sqrtf(szf[bb]) - sqrtf(sznt[bb]);
                lrot += dr * dr;
                const float dg = (vfb[bb] - vnb[bb]) * (1.0f / 6.0f);
                lgeo += dg * dg;
            }
            lrot *= (1.0f / (float)BB);
            lgeo *= (1.0f / (float)BB);

            out[0] = lrot + lref + la_c + la_f + lgeo;
        }
    }
}

extern "C" void kernel_launch(void* const* d_in, const int* in_sizes, int n_in,
                              void* d_out, int out_size)
{
    const float* sc = (const float*)d_in[0];  // source_coarse (B, 512, 3)
    const float* sf = (const float*)d_in[1];  // source_fine   (B, 8192, 3)
    const float* tp = (const float*)d_in[2];  // target_points (B, 8192, 3)
    float* out = (float*)d_out;

    dim3 g1(272, BB);
    nn_kernel<<<g1, NT>>>(sc, sf, tp);

    dim3 g2(66, BB);
    combine_kernel<<<g2, NT>>>(sc, sf, tp, out);
}

// round 16
// speedup vs baseline: 1.1995x; 1.1202x over previous
#include <cuda_runtime.h>
#include <math.h>

// Problem shapes (fixed by the dataset)
#define BB    2
#define NC    512
#define NF    8192
#define MM    8192
#define NT    256       // combine kernel block size
#define NTN   128       // nn kernel block size (finer scheduling granularity)
#define SLICE 512       // targets per block slice
#define NSL   16        // slices (8192 / 512)
#define QPT   4         // queries per thread (all nn roles)
#define EPSF  1e-12f

typedef unsigned long long ull;

// ---------------- scratch (__device__ globals; no allocation allowed) ----------------
__device__ float g_av [BB][NSL][NF];     // fine->target partial min value per slice
__device__ int   g_ai [BB][NSL][NF];     // fine->target partial argmin index per slice
__device__ float g_tv [BB][NSL][MM];     // target->fine partial min per slice
__device__ float g_tcv[BB][NSL][MM];     // target->coarse partial min per slice
__device__ float g_cv [BB][NSL][NC];     // coarse->target partial min per slice
__device__ float g_nt [BB * NF * 3];     // gathered nearest target per fine point
__device__ float g_pf [BB][32][4];       // fine combine: sum d1, sum zf^2, sum znt^2, sum ydiff^2
__device__ float g_pt [BB][32][2];       // target combine: sum d2f, sum d2c
__device__ float g_pc [BB][2];           // coarse combine: sum d1c
__device__ float g_pv [BB][32][2];       // volume partials (interior triples)
__device__ unsigned int g_ticket;        // finalize ticket (wraps -> self-reset)

// ---------------- packed f32x2 helpers (per-half bit-identical to scalar) ----------------
__device__ __forceinline__ ull pack2(float lo, float hi) {
    ull r; asm("mov.b64 %0, {%1, %2};" : "=l"(r) : "f"(lo), "f"(hi)); return r;
}
__device__ __forceinline__ void unpack2(ull v, float& lo, float& hi) {
    asm("mov.b64 {%0, %1}, %2;" : "=f"(lo), "=f"(hi) : "l"(v));
}
__device__ __forceinline__ ull mul2(ull a, ull b) {
    ull r; asm("mul.rn.f32x2 %0, %1, %2;" : "=l"(r) : "l"(a), "l"(b)); return r;
}
__device__ __forceinline__ ull fma2(ull a, ull b, ull c) {
    ull r; asm("fma.rn.f32x2 %0, %1, %2, %3;" : "=l"(r) : "l"(a), "l"(b), "l"(c)); return r;
}

// Warp sum (fixed shfl order -> deterministic); result valid on lane 0.
__device__ __forceinline__ float warpSum(float v) {
#pragma unroll
    for (int o = 16; o > 0; o >>= 1) v += __shfl_down_sync(0xFFFFFFFFu, v, o);
    return v;
}

// Six block sums with ONE barrier (combine kernel, NT threads). tid-0 result.
__device__ __forceinline__ void blockSum6(float* v, float (*sh)[6]) {
    const int lane = threadIdx.x & 31;
    const int w    = threadIdx.x >> 5;
#pragma unroll
    for (int i = 0; i < 6; i++) v[i] = warpSum(v[i]);
    if (lane == 0) {
#pragma unroll
        for (int i = 0; i < 6; i++) sh[w][i] = v[i];
    }
    __syncthreads();
    if (threadIdx.x == 0) {
#pragma unroll
        for (int i = 0; i < 6; i++) {
            float r = 0.0f;
#pragma unroll
            for (int k = 0; k < NT / 32; k++) r += sh[k][i];
            v[i] = r;
        }
    }
    __syncthreads();
}

// RAW pairs (argmin role — arithmetic must match the verified form exactly):
__device__ __forceinline__ void loadPairsRaw(ulonglong2* xy, ulonglong2* zw,
                                             const float* __restrict__ src,
                                             int t0, int count) {
    for (int p = threadIdx.x; p < count / 2; p += NTN) {
        const int j0 = t0 + 2 * p;
        const float x0 = src[j0 * 3 + 0], y0 = src[j0 * 3 + 1], z0 = src[j0 * 3 + 2];
        const float x1 = src[j0 * 3 + 3], y1 = src[j0 * 3 + 4], z1 = src[j0 * 3 + 5];
        ulonglong2 a, b;
        a.x = pack2(x0, x1); a.y = pack2(y0, y1);
        b.x = pack2(z0, z1);
        b.y = pack2(x0 * x0 + y0 * y0 + z0 * z0,
                    x1 * x1 + y1 * y1 + z1 * z1);
        xy[p] = a; zw[p] = b;
    }
}

// SCALED pairs (min-only roles): (-2x, -2y, -2z, |p|^2) -> 3 fma2 per pair.
__device__ __forceinline__ void loadPairsScaled(ulonglong2* xy, ulonglong2* zw,
                                                const float* __restrict__ src,
                                                int t0, int count) {
    for (int p = threadIdx.x; p < count / 2; p += NTN) {
        const int j0 = t0 + 2 * p;
        const float x0 = src[j0 * 3 + 0], y0 = src[j0 * 3 + 1], z0 = src[j0 * 3 + 2];
        const float x1 = src[j0 * 3 + 3], y1 = src[j0 * 3 + 4], z1 = src[j0 * 3 + 5];
        ulonglong2 a, b;
        a.x = pack2(-2.0f * x0, -2.0f * x1);
        a.y = pack2(-2.0f * y0, -2.0f * y1);
        b.x = pack2(-2.0f * z0, -2.0f * z1);
        b.y = pack2(x0 * x0 + y0 * y0 + z0 * z0,
                    x1 * x1 + y1 * y1 + z1 * z1);
        xy[p] = a; zw[p] = b;
    }
}

// EXACT verified distance for the argmin role:
//   xy = fma(qz,z, fma(qy,y, qx*x)); t = fma(-2, xy, w)
__device__ __forceinline__ ull distExact(ull qx2, ull qy2, ull qz2, ull NEG2,
                                         ulonglong2 vxy, ulonglong2 vzw) {
    const ull xy2 = fma2(qz2, vzw.x, fma2(qy2, vxy.y, mul2(qx2, vxy.x)));
    return fma2(NEG2, xy2, vzw.y);
}

// Main pass: grid = (528, BB), 128-thread blocks.
//  bx in [0,256):    fine->target argmin.  qblock = bx>>4 (0..15), slice = bx&15
//  bx in [256,512):  target->{fine,coarse} min. same decomposition
//  bx in [512,528):  coarse->target min. slice = bx-512, 512 coarse queries (QPT=4)
__global__ void __launch_bounds__(NTN) nn_kernel(const float* __restrict__ sc,
                                                 const float* __restrict__ sf,
                                                 const float* __restrict__ tp)
{
    __shared__ ulonglong2 tXY[SLICE / 2], tZW[SLICE / 2];
    __shared__ ulonglong2 cXY[16], cZW[16];   // coarse sub-slice (32 points)

    const int b   = blockIdx.y;
    const int bx  = blockIdx.x;
    const int tid = threadIdx.x;

    const float* tgt = tp + (size_t)b * MM * 3;
    const float* fin = sf + (size_t)b * NF * 3;
    const float* crs = sc + (size_t)b * NC * 3;

    if (bx < 256) {
        // ====== fine -> target : partial argmin, group-of-2-pairs tournament ======
        const int qb    = bx >> 4;
        const int slice = bx & 15;
        const int base  = slice * SLICE;

        loadPairsRaw(tXY, tZW, tgt, base, SLICE);

        ull qx2[QPT], qy2[QPT], qz2[QPT];
        float best[QPT];
        int   pb[QPT];
#pragma unroll
        for (int q = 0; q < QPT; q++) {
            const int qi = qb * (NTN * QPT) + q * NTN + tid;
            const float qx = fin[qi * 3 + 0];
            const float qy = fin[qi * 3 + 1];
            const float qz = fin[qi * 3 + 2];
            qx2[q] = pack2(qx, qx); qy2[q] = pack2(qy, qy); qz2[q] = pack2(qz, qz);
            best[q] = 3.0e38f; pb[q] = 0;
        }
        const ull NEG2 = pack2(-2.0f, -2.0f);
        __syncthreads();

#pragma unroll 4
        for (int p = 0; p < SLICE / 2; p += 2) {
            const ulonglong2 vxyA = tXY[p],     vzwA = tZW[p];
            const ulonglong2 vxyB = tXY[p + 1], vzwB = tZW[p + 1];
#pragma unroll
            for (int q = 0; q < QPT; q++) {
                const ull tA = distExact(qx2[q], qy2[q], qz2[q], NEG2, vxyA, vzwA);
                const ull tB = distExact(qx2[q], qy2[q], qz2[q], NEG2, vxyB, vzwB);
                float a0, a1, b0, b1;
                unpack2(tA, a0, a1);
                unpack2(tB, b0, b1);
                const float gm = fminf(fminf(a0, a1), fminf(b0, b1));
                if (gm < best[q]) { best[q] = gm; pb[q] = p; }
            }
        }
#pragma unroll
        for (int q = 0; q < QPT; q++) {
            const int qi = qb * (NTN * QPT) + q * NTN + tid;
            const int p = pb[q];
            const ulonglong2 vxyA = tXY[p],     vzwA = tZW[p];
            const ulonglong2 vxyB = tXY[p + 1], vzwB = tZW[p + 1];
            const ull tA = distExact(qx2[q], qy2[q], qz2[q], NEG2, vxyA, vzwA);
            const ull tB = distExact(qx2[q], qy2[q], qz2[q], NEG2, vxyB, vzwB);
            float a0, a1, b0, b1;
            unpack2(tA, a0, a1);
            unpack2(tB, b0, b1);
            const float m = best[q];
            // first index (ascending) whose distance equals the group min
            int off;
            if      (a0 == m) off = 0;
            else if (a1 == m) off = 1;
            else if (b0 == m) off = 2;
            else              off = 3;
            g_av[b][slice][qi] = m;
            g_ai[b][slice][qi] = base + 2 * p + off;
        }
    } else if (bx < 512) {
        // ====== target -> fine (min) and target -> coarse (min) — verified loop ======
        const int r     = bx - 256;
        const int qb    = r >> 4;
        const int slice = r & 15;

        loadPairsScaled(tXY, tZW, fin, slice * SLICE, SLICE);
        loadPairsScaled(cXY, cZW, crs, slice * 32, 32);

        ull qx2[QPT], qy2[QPT], qz2[QPT];
        float mf[QPT * 2], mc[QPT * 2];
#pragma unroll
        for (int q = 0; q < QPT; q++) {
            const int qj = qb * (NTN * QPT) + q * NTN + tid;
            const float qx = tgt[qj * 3 + 0];
            const float qy = tgt[qj * 3 + 1];
            const float qz = tgt[qj * 3 + 2];
            qx2[q] = pack2(qx, qx); qy2[q] = pack2(qy, qy); qz2[q] = pack2(qz, qz);
            mf[2 * q] = 3.0e38f; mf[2 * q + 1] = 3.0e38f;
            mc[2 * q] = 3.0e38f; mc[2 * q + 1] = 3.0e38f;
        }
        __syncthreads();

#pragma unroll 4
        for (int p = 0; p < SLICE / 2; p++) {
            const ulonglong2 vxy = tXY[p];
            const ulonglong2 vzw = tZW[p];
#pragma unroll
            for (int q = 0; q < QPT; q++) {
                const ull t2 = fma2(qx2[q], vxy.x, fma2(qy2[q], vxy.y, fma2(qz2[q], vzw.x, vzw.y)));
                float tlo, thi; unpack2(t2, tlo, thi);
                mf[2 * q]     = fminf(mf[2 * q],     tlo);
                mf[2 * q + 1] = fminf(mf[2 * q + 1], thi);
            }
        }
#pragma unroll
        for (int p = 0; p < 16; p++) {
            const ulonglong2 vxy = cXY[p];
            const ulonglong2 vzw = cZW[p];
#pragma unroll
            for (int q = 0; q < QPT; q++) {
                const ull t2 = fma2(qx2[q], vxy.x, fma2(qy2[q], vxy.y, fma2(qz2[q], vzw.x, vzw.y)));
                float tlo, thi; unpack2(t2, tlo, thi);
                mc[2 * q]     = fminf(mc[2 * q],     tlo);
                mc[2 * q + 1] = fminf(mc[2 * q + 1], thi);
            }
        }
#pragma unroll
        for (int q = 0; q < QPT; q++) {
            const int qj = qb * (NTN * QPT) + q * NTN + tid;
            g_tv [b][slice][qj] = fminf(mf[2 * q], mf[2 * q + 1]);
            g_tcv[b][slice][qj] = fminf(mc[2 * q], mc[2 * q + 1]);
        }
    } else {
        // ================= coarse -> target : partial min — verified loop =================
        const int slice = bx - 512;

        loadPairsScaled(tXY, tZW, tgt, slice * SLICE, SLICE);

        ull qx2[QPT], qy2[QPT], qz2[QPT];
        float m[QPT * 2];
#pragma unroll
        for (int q = 0; q < QPT; q++) {
            const int ci = q * NTN + tid;
            const float qx = crs[ci * 3 + 0];
            const float qy = crs[ci * 3 + 1];
            const float qz = crs[ci * 3 + 2];
            qx2[q] = pack2(qx, qx); qy2[q] = pack2(qy, qy); qz2[q] = pack2(qz, qz);
            m[2 * q] = 3.0e38f; m[2 * q + 1] = 3.0e38f;
        }
        __syncthreads();

#pragma unroll 4
        for (int p = 0; p < SLICE / 2; p++) {
            const ulonglong2 vxy = tXY[p];
            const ulonglong2 vzw = tZW[p];
#pragma unroll
            for (int q = 0; q < QPT; q++) {
                const ull t2 = fma2(qx2[q], vxy.x, fma2(qy2[q], vxy.y, fma2(qz2[q], vzw.x, vzw.y)));
                float tlo, thi; unpack2(t2, tlo, thi);
                m[2 * q]     = fminf(m[2 * q],     tlo);
                m[2 * q + 1] = fminf(m[2 * q + 1], thi);
            }
        }
#pragma unroll
        for (int q = 0; q < QPT; q++) {
            const int ci = q * NTN + tid;
            g_cv[b][slice][ci] = fminf(m[2 * q], m[2 * q + 1]);
        }
    }
}

// Combine + fused tail. grid = (66, BB). Last block (ticket) finalizes.
__global__ void __launch_bounds__(NT) combine_kernel(const float* __restrict__ sc,
                                                     const float* __restrict__ sf,
                                                     const float* __restrict__ tp,
                                                     float* __restrict__ out)
{
    __shared__ float s6[NT / 32][6];
    __shared__ float sfin[NT][3], snt[NT][3];
    __shared__ float svol[BB][2];
    __shared__ bool  s_last;
    const int b   = blockIdx.y;
    const int bx  = blockIdx.x;
    const int tid = threadIdx.x;

    float red[6] = {0, 0, 0, 0, 0, 0};

    if (bx < 32) {
        const int qi = bx * NT + tid;
        // tournament on (value, slice): ascending strict < keeps earliest slice
        float best = g_av[b][0][qi]; int sb = 0;
#pragma unroll
        for (int s = 1; s < NSL; s++) {
            const float v = g_av[b][s][qi];
            if (v < best) { best = v; sb = s; }
        }
        const int jb = g_ai[b][sb][qi];

        const float* fin = sf + (size_t)b * NF * 3;
        const float* tgt = tp + (size_t)b * MM * 3;
        const float qx = fin[qi * 3 + 0];
        const float qy = fin[qi * 3 + 1];
        const float qz = fin[qi * 3 + 2];
        const float qq = qx * qx + qy * qy + qz * qz;

        const float d  = fmaxf(qq + best, 0.0f);
        const float d1 = sqrtf(fmaxf(d, EPSF));

        const float nx = tgt[jb * 3 + 0];
        const float ny = tgt[jb * 3 + 1];
        const float nz = tgt[jb * 3 + 2];
        const int o = (b * NF + qi) * 3;
        g_nt[o + 0] = nx; g_nt[o + 1] = ny; g_nt[o + 2] = nz;

        sfin[tid][0] = qx; sfin[tid][1] = qy; sfin[tid][2] = qz;
        snt [tid][0] = nx; snt [tid][1] = ny; snt [tid][2] = nz;
        __syncthreads();

        float vf = 0.0f, vn = 0.0f;
        if (tid < NT - 2) {
            float a0 = sfin[tid][0],   a1 = sfin[tid][1],   a2 = sfin[tid][2];
            float e0 = sfin[tid+1][0], e1 = sfin[tid+1][1], e2 = sfin[tid+1][2];
            float c0 = sfin[tid+2][0], c1 = sfin[tid+2][1], c2 = sfin[tid+2][2];
            float cx = a1 * e2 - a2 * e1;
            float cy = a2 * e0 - a0 * e2;
            float cz = a0 * e1 - a1 * e0;
            vf = cx * c0 + cy * c1 + cz * c2;

            a0 = snt[tid][0];   a1 = snt[tid][1];   a2 = snt[tid][2];
            e0 = snt[tid+1][0]; e1 = snt[tid+1][1]; e2 = snt[tid+1][2];
            c0 = snt[tid+2][0]; c1 = snt[tid+2][1]; c2 = snt[tid+2][2];
            cx = a1 * e2 - a2 * e1;
            cy = a2 * e0 - a0 * e2;
            cz = a0 * e1 - a1 * e0;
            vn = cx * c0 + cy * c1 + cz * c2;
        }

        const float yd = qy - ny;
        red[0] = d1; red[1] = qz * qz; red[2] = nz * nz; red[3] = yd * yd;
        red[4] = vf; red[5] = vn;
        blockSum6(red, s6);
        if (tid == 0) {
            g_pf[b][bx][0] = red[0]; g_pf[b][bx][1] = red[1];
            g_pf[b][bx][2] = red[2]; g_pf[b][bx][3] = red[3];
            g_pv[b][bx][0] = red[4]; g_pv[b][bx][1] = red[5];
        }
    } else if (bx < 64) {
        const int qj = (bx - 32) * NT + tid;
        float mF = g_tv[b][0][qj], mC = g_tcv[b][0][qj];
#pragma unroll
        for (int s = 1; s < NSL; s++) {
            mF = fminf(mF, g_tv[b][s][qj]);
            mC = fminf(mC, g_tcv[b][s][qj]);
        }
        const float* tgt = tp + (size_t)b * MM * 3;
        const float qx = tgt[qj * 3 + 0];
        const float qy = tgt[qj * 3 + 1];
        const float qz = tgt[qj * 3 + 2];
        const float qq = qx * qx + qy * qy + qz * qz;

        red[0] = sqrtf(fmaxf(fmaxf(qq + mF, 0.0f), EPSF));
        red[1] = sqrtf(fmaxf(fmaxf(qq + mC, 0.0f), EPSF));
        blockSum6(red, s6);
        if (tid == 0) { g_pt[b][bx - 32][0] = red[0]; g_pt[b][bx - 32][1] = red[1]; }
    } else {
        const int ci = (bx - 64) * NT + tid;
        float m = g_cv[b][0][ci];
#pragma unroll
        for (int s = 1; s < NSL; s++) m = fminf(m, g_cv[b][s][ci]);

        const float* crs = sc + (size_t)b * NC * 3;
        const float qx = crs[ci * 3 + 0];
        const float qy = crs[ci * 3 + 1];
        const float qz = crs[ci * 3 + 2];
        const float qq = qx * qx + qy * qy + qz * qz;

        red[0] = sqrtf(fmaxf(fmaxf(qq + m, 0.0f), EPSF));
        blockSum6(red, s6);
        if (tid == 0) g_pc[b][bx - 64] = red[0];
    }

    // ---------------- last-block fused tail ----------------
    __threadfence();
    if (tid == 0) {
        const unsigned int total = 66 * BB;
        const unsigned int old = atomicInc(&g_ticket, total - 1);
        s_last = (old == total - 1);
    }
    __syncthreads();
    if (!s_last) return;

    // Boundary volume triples: i = 256*k + 254/255, k = 0..30 (62 per batch)
    for (int bb = 0; bb < BB; bb++) {
        float vf = 0.0f, vn = 0.0f;
        for (int t = tid; t < 62; t += NT) {
            const int k = t >> 1;
            const int i = 256 * k + 254 + (t & 1);
            const float* p = sf + (size_t)bb * NF * 3 + (size_t)i * 3;
            float a0 = p[0], a1 = p[1], a2 = p[2];
            float e0 = p[3], e1 = p[4], e2 = p[5];
            float c0 = p[6], c1 = p[7], c2 = p[8];
            float cx = a1 * e2 - a2 * e1;
            float cy = a2 * e0 - a0 * e2;
            float cz = a0 * e1 - a1 * e0;
            vf += cx * c0 + cy * c1 + cz * c2;

            const float* q = g_nt + ((size_t)bb * NF + i) * 3;
            a0 = q[0]; a1 = q[1]; a2 = q[2];
            e0 = q[3]; e1 = q[4]; e2 = q[5];
            c0 = q[6]; c1 = q[7]; c2 = q[8];
            cx = a1 * e2 - a2 * e1;
            cy = a2 * e0 - a0 * e2;
            cz = a0 * e1 - a1 * e0;
            vn += cx * c0 + cy * c1 + cz * c2;
        }
        float rv[6] = {vf, vn, 0, 0, 0, 0};
        blockSum6(rv, s6);
        if (tid == 0) { svol[bb][0] = rv[0]; svol[bb][1] = rv[1]; }
    }
    __syncthreads();

    // Parallel finalize: warp 0, lane k owns partial slot k.
    if (tid < 32) {
        float S1f = 0.0f, Syd = 0.0f, S2f = 0.0f, S2c = 0.0f;
        float szf[BB], sznt[BB], vfb[BB], vnb[BB];
#pragma unroll
        for (int bb = 0; bb < BB; bb++) {
            const float a0 = warpSum(g_pf[bb][tid][0]);
            const float a1 = warpSum(g_pf[bb][tid][1]);
            const float a2 = warpSum(g_pf[bb][tid][2]);
            const float a3 = warpSum(g_pf[bb][tid][3]);
            const float b0 = warpSum(g_pt[bb][tid][0]);
            const float b1 = warpSum(g_pt[bb][tid][1]);
            const float v0 = warpSum(g_pv[bb][tid][0]);
            const float v1 = warpSum(g_pv[bb][tid][1]);
            if (tid == 0) {
                S1f += a0; szf[bb] = a1; sznt[bb] = a2; Syd += a3;
                S2f += b0; S2c += b1;
                vfb[bb] = v0 + svol[bb][0];
                vnb[bb] = v1 + svol[bb][1];
            }
        }
        if (tid == 0) {
            float S1c = 0.0f;
#pragma unroll
            for (int bb = 0; bb < BB; bb++) S1c += g_pc[bb][0] + g_pc[bb][1];

            const float la_f = 0.5f * (S1f / (float)(BB * NF) + S2f / (float)(BB * MM));
            const float la_c = 0.5f * (S1c / (float)(BB * NC) + S2c / (float)(BB * MM));
            const float lref = Syd / (float)(BB * NF);

            float lrot = 0.0f, lgeo = 0.0f;
#pragma unroll
            for (int bb = 0; bb < BB; bb++) {
                const float dr = sqrtf(szf[bb]) - sqrtf(sznt[bb]);
                lrot += dr * dr;
                const float dg = (vfb[bb] - vnb[bb]) * (1.0f / 6.0f);
                lgeo += dg * dg;
            }
            lrot *= (1.0f / (float)BB);
            lgeo *= (1.0f / (float)BB);

            out[0] = lrot + lref + la_c + la_f + lgeo;
        }
    }
}

extern "C" void kernel_launch(void* const* d_in, const int* in_sizes, int n_in,
                              void* d_out, int out_size)
{
    const float* sc = (const float*)d_in[0];  // source_coarse (B, 512, 3)
    const float* sf = (const float*)d_in[1];  // source_fine   (B, 8192, 3)
    const float* tp = (const float*)d_in[2];  // target_points (B, 8192, 3)
    float* out = (float*)d_out;

    dim3 g1(528, BB);
    nn_kernel<<<g1, NTN>>>(sc, sf, tp);

    dim3 g2(66, BB);
    combine_kernel<<<g2, NT>>>(sc, sf, tp, out);
}